// round 16
// baseline (speedup 1.0000x reference)
#include <cuda_runtime.h>
#include <cuda_fp16.h>
#include <math.h>
#include <stdint.h>

#define B_   32
#define L_   256
#define DM_  512
#define FF_  2048
#define E_   8
#define NPAIR 64

// ---------------- device scratch (static = allocation-free) ----------------
__device__ int   g_pair_e[NPAIR];
__device__ float g_pair_g[NPAIR];
// x single fp16: [B*L][DM]
__device__ __align__(256) __half g_x[(size_t)B_ * L_ * DM_];
// W1^T single fp16: [E][FF][DM]
__device__ __align__(256) __half g_w1t[(size_t)E_ * FF_ * DM_];
// W2^T single fp16: [E][DM][FF]
__device__ __align__(256) __half g_w2t[(size_t)E_ * DM_ * FF_];
// g*gelu(h) single fp16: [pair][L][FF]
__device__ __align__(256) __half g_gh[(size_t)NPAIR * L_ * FF_];
// per-pair fp32 partials of GEMM2 (slot-split)
__device__ __align__(256) float g_part[(size_t)NPAIR * L_ * DM_];

// ---------------- helpers ----------------
__device__ __forceinline__ uint32_t smem_u32(const void* p) {
    uint32_t a;
    asm("{ .reg .u64 t; cvta.to.shared.u64 t, %1; cvt.u32.u64 %0, t; }" : "=r"(a) : "l"(p));
    return a;
}
__device__ __forceinline__ void cp16(uint32_t dst, const void* src) {
    asm volatile("cp.async.cg.shared.global [%0], [%1], 16;" :: "r"(dst), "l"(src));
}
#define CP_COMMIT() asm volatile("cp.async.commit_group;" ::: "memory")

__device__ __forceinline__ void ldsm_x4(uint32_t& r0, uint32_t& r1, uint32_t& r2, uint32_t& r3, uint32_t a) {
    asm volatile("ldmatrix.sync.aligned.m8n8.x4.shared.b16 {%0,%1,%2,%3}, [%4];"
                 : "=r"(r0), "=r"(r1), "=r"(r2), "=r"(r3) : "r"(a));
}
__device__ __forceinline__ void mma_f16(float* c, const uint32_t* a, uint32_t b0, uint32_t b1) {
    asm volatile("mma.sync.aligned.m16n8k16.row.col.f32.f16.f16.f32 "
                 "{%0,%1,%2,%3}, {%4,%5,%6,%7}, {%8,%9}, {%0,%1,%2,%3};"
                 : "+f"(c[0]), "+f"(c[1]), "+f"(c[2]), "+f"(c[3])
                 : "r"(a[0]), "r"(a[1]), "r"(a[2]), "r"(a[3]), "r"(b0), "r"(b1));
}
__device__ __forceinline__ float gelu_exact(float x) {
    return 0.5f * x * (1.0f + erff(x * 0.70710678118654752440f));
}

// Load a ROWS x 64 fp16 tile (128B rows, XOR swizzle chunk^=(row&7)) via cp.async.
template<int ROWS, int NT>
__device__ __forceinline__ void load_tile(uint32_t dst, const __half* src, int ld, int tid) {
    constexpr int ITER = ROWS * 8 / NT;
#pragma unroll
    for (int j = 0; j < ITER; j++) {
        int idx = tid + j * NT;
        int r = idx >> 3, c = idx & 7;
        uint32_t off = (uint32_t)(r * 128 + ((c ^ (r & 7)) * 16));
        cp16(dst + off, (const char*)src + (size_t)r * ld * 2 + c * 16);
    }
}

// 1-term chunk: acc += A*B over warp tile (MF*16) x (NF*8), kc=64.
template<int MF, int NF>
__device__ __forceinline__ void compute_single(float (&acc)[MF][NF][4],
                                               uint32_t aA, uint32_t bB,
                                               int wm, int wn, int lane) {
#pragma unroll
    for (int ks = 0; ks < 4; ks++) {
        uint32_t af[MF][4];
#pragma unroll
        for (int mf = 0; mf < MF; mf++) {
            int r = wm + mf * 16 + (lane & 15);
            int c = ks * 2 + (lane >> 4);
            uint32_t off = (uint32_t)(r * 128 + ((c ^ (r & 7)) * 16));
            ldsm_x4(af[mf][0], af[mf][1], af[mf][2], af[mf][3], aA + off);
        }
#pragma unroll
        for (int nfp = 0; nfp < NF / 2; nfp++) {
            int q = lane >> 3;
            int r = wn + (nfp * 2 + (q >> 1)) * 8 + (lane & 7);
            int c = ks * 2 + (q & 1);
            uint32_t off = (uint32_t)(r * 128 + ((c ^ (r & 7)) * 16));
            uint32_t b0, b1, b2, b3;
            ldsm_x4(b0, b1, b2, b3, bB + off);
#pragma unroll
            for (int mf = 0; mf < MF; mf++) {
                mma_f16(acc[mf][2 * nfp],     af[mf], b0, b1);
                mma_f16(acc[mf][2 * nfp + 1], af[mf], b2, b3);
            }
        }
    }
}

// ---------------------------------------------------------------------------
// Fused prep: gates + x fp16 cvt (float4) + W1^T fp16 + W2^T fp16.
// ---------------------------------------------------------------------------
__device__ __forceinline__ void transpose_sec(const float* __restrict__ W,
                                              __half* __restrict__ T,
                                              int K, int N, int bx, int by, int bz,
                                              int tx, int ty, float (*s)[33]) {
    int n0 = bx * 32, k0 = by * 32;
    const float* Wp = W + (size_t)bz * K * N;
#pragma unroll
    for (int i = 0; i < 32; i += 8)
        s[ty + i][tx] = Wp[(size_t)(k0 + ty + i) * N + n0 + tx];
    __syncthreads();
#pragma unroll
    for (int i = 0; i < 32; i += 8) {
        int n = n0 + ty + i;
        int k = k0 + tx;
        T[((size_t)bz * N + n) * K + k] = __float2half(s[tx][ty + i]);
    }
}

__global__ void prep_kernel(const float* __restrict__ X,
                            const float* __restrict__ logits,
                            const int*   __restrict__ masks,
                            const float* __restrict__ W1,
                            const float* __restrict__ W2) {
    __shared__ float s[32][33];
    const int blk = blockIdx.x;
    const int tid = threadIdx.x;
    const int tx = tid & 31, ty = tid >> 5;

    if (blk < 4096) {
        // x -> fp16, 4 elems/thread via float4
        size_t i4 = (size_t)blk * 256 + tid;
        float4 v = ((const float4*)X)[i4];
        __half hh[4] = {__float2half(v.x), __float2half(v.y),
                        __float2half(v.z), __float2half(v.w)};
        *(uint2*)(g_x + i4 * 4) = *(uint2*)hh;
    } else if (blk < 12288) {
        int i = blk - 4096;                        // W1: bx<64, by<16, bz<8
        transpose_sec(W1, g_w1t, DM_, FF_, i & 63, (i >> 6) & 15, i >> 10, tx, ty, s);
    } else if (blk < 20480) {
        int i = blk - 12288;                       // W2: bx<16, by<64, bz<8
        transpose_sec(W2, g_w2t, FF_, DM_, i & 15, (i >> 4) & 63, i >> 10, tx, ty, s);
    } else {
        // gates
        int b = tid;
        if (b >= B_) return;
        float p[E_];
        float mx = -1e30f;
#pragma unroll
        for (int i = 0; i < E_; i++) { p[i] = logits[b * E_ + i]; mx = fmaxf(mx, p[i]); }
        float sum = 0.0f;
#pragma unroll
        for (int i = 0; i < E_; i++) { p[i] = expf(p[i] - mx); sum += p[i]; }
        float inv = 1.0f / sum;
#pragma unroll
        for (int i = 0; i < E_; i++) p[i] = (masks[b * E_ + i] == 1) ? p[i] * inv : 0.0f;
        int i1 = 0;
#pragma unroll
        for (int i = 1; i < E_; i++) if (p[i] > p[i1]) i1 = i;
        int i2 = -1;
#pragma unroll
        for (int i = 0; i < E_; i++) {
            if (i == i1) continue;
            if (i2 < 0 || p[i] > p[i2]) i2 = i;
        }
        float denom = p[i1] + p[i2] + 1e-9f;
        g_pair_e[2 * b + 0] = i1;  g_pair_g[2 * b + 0] = p[i1] / denom;
        g_pair_e[2 * b + 1] = i2;  g_pair_g[2 * b + 1] = p[i2] / denom;
    }
}

// ---------------------------------------------------------------------------
// GEMM1 (fp16 1-term): gh[pair] = fp16( g * gelu(x[b] @ W1[e] + b1[e]) )
// BM=128, BN=256, kc=64; stage = A16+B32 = 48KB; 3 stages (144KB), 1 sync/iter.
// 256 threads, warp tile 64x64 (MF=4, NF=8). Grid (8,2,64) = 1024 CTAs.
// ---------------------------------------------------------------------------
#define G1_STAGE  49152u
#define G1_B_O    16384u
#define G1_SMEM   (3 * 49152)

__global__ void __launch_bounds__(256, 1)
gemm1_mma(const float* __restrict__ b1p) {
    extern __shared__ __align__(128) char smem[];
    const int tid = threadIdx.x, lane = tid & 31, wid = tid >> 5;
    const int pair = blockIdx.z;
    const int e = g_pair_e[pair];
    const float g = g_pair_g[pair];
    const int m0 = blockIdx.y * 128, n0 = blockIdx.x * 256;

    const __half* Abase = g_x   + ((size_t)(pair >> 1) * L_ + m0) * DM_;
    const __half* Bbase = g_w1t + ((size_t)e * FF_ + n0) * DM_;

    uint32_t s0 = smem_u32(smem);
    const int wm = (wid >> 2) * 64, wn = (wid & 3) * 64;   // warp tile 64x64

    float acc[4][8][4] = {};
    const int NC = 8;   // 512 / 64

#define G1_LOAD(c, buf) do { int _k = (c) * 64; uint32_t _d = s0 + (buf) * G1_STAGE; \
        load_tile<128, 256>(_d,          Abase + _k, DM_, tid); \
        load_tile<256, 256>(_d + G1_B_O, Bbase + _k, DM_, tid); \
        CP_COMMIT(); } while (0)

    G1_LOAD(0, 0);
    G1_LOAD(1, 1);
    for (int c = 0; c < NC; c++) {
        if (c == NC - 1) asm volatile("cp.async.wait_group 0;" ::: "memory");
        else             asm volatile("cp.async.wait_group 1;" ::: "memory");
        __syncthreads();
        if (c + 2 < NC) G1_LOAD(c + 2, (uint32_t)((c + 2) % 3));
        uint32_t sb = s0 + (uint32_t)(c % 3) * G1_STAGE;
        compute_single<4, 8>(acc, sb, sb + G1_B_O, wm, wn, lane);
    }
#undef G1_LOAD

    // epilogue: +bias, gelu, *gate, store single fp16
    const float* b1e = b1p + (size_t)e * FF_;
#pragma unroll
    for (int mf = 0; mf < 4; mf++) {
#pragma unroll
        for (int h = 0; h < 2; h++) {
            int r = m0 + wm + mf * 16 + (lane >> 2) + 8 * h;
            __half* rowp = g_gh + ((size_t)pair * L_ + r) * FF_;
#pragma unroll
            for (int nf = 0; nf < 8; nf++) {
                int n = n0 + wn + nf * 8 + (lane & 3) * 2;
                float v0 = acc[mf][nf][2 * h + 0] + __ldg(b1e + n);
                float v1 = acc[mf][nf][2 * h + 1] + __ldg(b1e + n + 1);
                __half hv[2] = {__float2half(gelu_exact(v0) * g),
                                __float2half(gelu_exact(v1) * g)};
                *(uint32_t*)(rowp + n) = *(uint32_t*)hv;
            }
        }
    }
}

// ---------------------------------------------------------------------------
// GEMM2 (fp16 1-term, slot-split, BN=128): part[pair] = gh[pair] @ W2[e_pair]
// BM=128, BN=128, kc=64; stage = A16+B16 = 32KB; 3 stages (96KB) -> 2 CTAs/SM.
// 256 threads, 8 warps 2x4, warp tile 64x32 (MF=4, NF=4). Grid (4,2,64) = 512.
// K = 2048 (32 chunks); 1 sync/iter. A-traffic halved vs BN=64.
// ---------------------------------------------------------------------------
#define H2_STAGE  32768u
#define H2_B_O    16384u
#define H2_SMEM   (3 * 32768)

__global__ void __launch_bounds__(256, 2)
gemm2_mma() {
    extern __shared__ __align__(128) char smem[];
    const int tid = threadIdx.x, lane = tid & 31, wid = tid >> 5;
    const int pair = blockIdx.z;
    const int e = g_pair_e[pair];
    const int m0 = blockIdx.y * 128, n0 = blockIdx.x * 128;

    const __half* Abase = g_gh  + ((size_t)pair * L_ + m0) * FF_;
    const __half* Bbase = g_w2t + ((size_t)e * DM_ + n0) * FF_;

    uint32_t s0 = smem_u32(smem);
    const int wm = (wid >> 2) * 64, wn = (wid & 3) * 32;   // warp tile 64x32

    float acc[4][4][4] = {};
    const int NC = 32;   // 2048 / 64

#define G2_LOAD(c, buf) do { int _k = (c) * 64; uint32_t _d = s0 + (buf) * H2_STAGE; \
        load_tile<128, 256>(_d,          Abase + _k, FF_, tid); \
        load_tile<128, 256>(_d + H2_B_O, Bbase + _k, FF_, tid); \
        CP_COMMIT(); } while (0)

    G2_LOAD(0, 0);
    G2_LOAD(1, 1);
    for (int c = 0; c < NC; c++) {
        if (c == NC - 1) asm volatile("cp.async.wait_group 0;" ::: "memory");
        else             asm volatile("cp.async.wait_group 1;" ::: "memory");
        __syncthreads();
        if (c + 2 < NC) G2_LOAD(c + 2, (uint32_t)((c + 2) % 3));
        uint32_t sb = s0 + (uint32_t)(c % 3) * H2_STAGE;
        compute_single<4, 4>(acc, sb, sb + H2_B_O, wm, wn, lane);
    }
#undef G2_LOAD

    // store fp32 partials (bias added in combine)
#pragma unroll
    for (int mf = 0; mf < 4; mf++) {
#pragma unroll
        for (int h = 0; h < 2; h++) {
            int r = wm + mf * 16 + (lane >> 2) + 8 * h;
            float* op = g_part + ((size_t)pair * L_ + m0 + r) * DM_;
#pragma unroll
            for (int nf = 0; nf < 4; nf++) {
                int n = n0 + wn + nf * 8 + (lane & 3) * 2;
                float2 v;
                v.x = acc[mf][nf][2 * h + 0];
                v.y = acc[mf][nf][2 * h + 1];
                *(float2*)(op + n) = v;
            }
        }
    }
}

// ---------------------------------------------------------------------------
// combine: out[b,l,:] = part[2b] + part[2b+1] + g0*b2[e0] + g1*b2[e1]
// ---------------------------------------------------------------------------
__global__ void combine_kernel(const float* __restrict__ b2p, float* __restrict__ out) {
    size_t i = (size_t)blockIdx.x * blockDim.x + threadIdx.x;
    size_t row = i / (DM_ / 4);
    int n4 = (int)(i % (DM_ / 4));
    int b = (int)(row / L_);
    int e0 = g_pair_e[2 * b + 0], e1 = g_pair_e[2 * b + 1];
    float g0 = g_pair_g[2 * b + 0], g1 = g_pair_g[2 * b + 1];

    const float4* p0 = (const float4*)(g_part + ((size_t)(2 * b + 0) * L_ + (row % L_)) * DM_);
    const float4* p1 = (const float4*)(g_part + ((size_t)(2 * b + 1) * L_ + (row % L_)) * DM_);
    const float4* bb0 = (const float4*)(b2p + (size_t)e0 * DM_);
    const float4* bb1 = (const float4*)(b2p + (size_t)e1 * DM_);

    float4 a = p0[n4], c = p1[n4], d0 = __ldg(bb0 + n4), d1 = __ldg(bb1 + n4);
    float4 r;
    r.x = a.x + c.x + g0 * d0.x + g1 * d1.x;
    r.y = a.y + c.y + g0 * d0.y + g1 * d1.y;
    r.z = a.z + c.z + g0 * d0.z + g1 * d1.z;
    r.w = a.w + c.w + g0 * d0.w + g1 * d1.w;
    ((float4*)out)[i] = r;
}

// ---------------------------------------------------------------------------
// launch — kernel launches + idempotent attribute opt-ins (no statics)
// ---------------------------------------------------------------------------
extern "C" void kernel_launch(void* const* d_in, const int* in_sizes, int n_in,
                              void* d_out, int out_size) {
    const float* x      = (const float*)d_in[0];
    const float* logits = (const float*)d_in[1];
    const int*   masks  = (const int*)  d_in[2];
    const float* W1     = (const float*)d_in[3];
    const float* b1     = (const float*)d_in[4];
    const float* W2     = (const float*)d_in[5];
    const float* b2     = (const float*)d_in[6];
    float* out = (float*)d_out;

    cudaFuncSetAttribute(gemm1_mma, cudaFuncAttributeMaxDynamicSharedMemorySize, G1_SMEM);
    cudaFuncSetAttribute(gemm2_mma, cudaFuncAttributeMaxDynamicSharedMemorySize, H2_SMEM);

    prep_kernel<<<20481, 256>>>(x, logits, masks, W1, W2);

    gemm1_mma<<<dim3(FF_ / 256, L_ / 128, NPAIR), 256, G1_SMEM>>>(b1);
    gemm2_mma<<<dim3(DM_ / 128, L_ / 128, NPAIR), 256, H2_SMEM>>>();

    size_t nq = (size_t)B_ * L_ * DM_ / 4;
    combine_kernel<<<(unsigned)((nq + 255) / 256), 256>>>(b2, out);
}

// round 17
// speedup vs baseline: 1.0545x; 1.0545x over previous
#include <cuda_runtime.h>
#include <cuda_fp16.h>
#include <math.h>
#include <stdint.h>

#define B_   32
#define L_   256
#define DM_  512
#define FF_  2048
#define E_   8
#define NPAIR 64

// ---------------- device scratch (static = allocation-free) ----------------
__device__ int   g_pair_e[NPAIR];
__device__ float g_pair_g[NPAIR];
// x single fp16: [B*L][DM]
__device__ __align__(256) __half g_x[(size_t)B_ * L_ * DM_];
// W1^T single fp16: [E][FF][DM]
__device__ __align__(256) __half g_w1t[(size_t)E_ * FF_ * DM_];
// W2^T single fp16: [E][DM][FF]
__device__ __align__(256) __half g_w2t[(size_t)E_ * DM_ * FF_];
// g*gelu(h) single fp16: [pair][L][FF]
__device__ __align__(256) __half g_gh[(size_t)NPAIR * L_ * FF_];

// ---------------- helpers ----------------
__device__ __forceinline__ uint32_t smem_u32(const void* p) {
    uint32_t a;
    asm("{ .reg .u64 t; cvta.to.shared.u64 t, %1; cvt.u32.u64 %0, t; }" : "=r"(a) : "l"(p));
    return a;
}
__device__ __forceinline__ void cp16(uint32_t dst, const void* src) {
    asm volatile("cp.async.cg.shared.global [%0], [%1], 16;" :: "r"(dst), "l"(src));
}
#define CP_COMMIT() asm volatile("cp.async.commit_group;" ::: "memory")

__device__ __forceinline__ void ldsm_x4(uint32_t& r0, uint32_t& r1, uint32_t& r2, uint32_t& r3, uint32_t a) {
    asm volatile("ldmatrix.sync.aligned.m8n8.x4.shared.b16 {%0,%1,%2,%3}, [%4];"
                 : "=r"(r0), "=r"(r1), "=r"(r2), "=r"(r3) : "r"(a));
}
__device__ __forceinline__ void mma_f16(float* c, const uint32_t* a, uint32_t b0, uint32_t b1) {
    asm volatile("mma.sync.aligned.m16n8k16.row.col.f32.f16.f16.f32 "
                 "{%0,%1,%2,%3}, {%4,%5,%6,%7}, {%8,%9}, {%0,%1,%2,%3};"
                 : "+f"(c[0]), "+f"(c[1]), "+f"(c[2]), "+f"(c[3])
                 : "r"(a[0]), "r"(a[1]), "r"(a[2]), "r"(a[3]), "r"(b0), "r"(b1));
}
__device__ __forceinline__ float gelu_exact(float x) {
    return 0.5f * x * (1.0f + erff(x * 0.70710678118654752440f));
}

// Load a ROWS x 64 fp16 tile (128B rows, XOR swizzle chunk^=(row&7)) via cp.async.
template<int ROWS, int NT>
__device__ __forceinline__ void load_tile(uint32_t dst, const __half* src, int ld, int tid) {
    constexpr int ITER = ROWS * 8 / NT;
#pragma unroll
    for (int j = 0; j < ITER; j++) {
        int idx = tid + j * NT;
        int r = idx >> 3, c = idx & 7;
        uint32_t off = (uint32_t)(r * 128 + ((c ^ (r & 7)) * 16));
        cp16(dst + off, (const char*)src + (size_t)r * ld * 2 + c * 16);
    }
}

// 1-term chunk: acc += A*B over warp tile (MF*16) x (NF*8), kc=64.
template<int MF, int NF>
__device__ __forceinline__ void compute_single(float (&acc)[MF][NF][4],
                                               uint32_t aA, uint32_t bB,
                                               int wm, int wn, int lane) {
#pragma unroll
    for (int ks = 0; ks < 4; ks++) {
        uint32_t af[MF][4];
#pragma unroll
        for (int mf = 0; mf < MF; mf++) {
            int r = wm + mf * 16 + (lane & 15);
            int c = ks * 2 + (lane >> 4);
            uint32_t off = (uint32_t)(r * 128 + ((c ^ (r & 7)) * 16));
            ldsm_x4(af[mf][0], af[mf][1], af[mf][2], af[mf][3], aA + off);
        }
#pragma unroll
        for (int nfp = 0; nfp < NF / 2; nfp++) {
            int q = lane >> 3;
            int r = wn + (nfp * 2 + (q >> 1)) * 8 + (lane & 7);
            int c = ks * 2 + (q & 1);
            uint32_t off = (uint32_t)(r * 128 + ((c ^ (r & 7)) * 16));
            uint32_t b0, b1, b2, b3;
            ldsm_x4(b0, b1, b2, b3, bB + off);
#pragma unroll
            for (int mf = 0; mf < MF; mf++) {
                mma_f16(acc[mf][2 * nfp],     af[mf], b0, b1);
                mma_f16(acc[mf][2 * nfp + 1], af[mf], b2, b3);
            }
        }
    }
}

// ---------------------------------------------------------------------------
// Fused prep: gates + x fp16 cvt (float4) + W1^T fp16 + W2^T fp16.
// ---------------------------------------------------------------------------
__device__ __forceinline__ void transpose_sec(const float* __restrict__ W,
                                              __half* __restrict__ T,
                                              int K, int N, int bx, int by, int bz,
                                              int tx, int ty, float (*s)[33]) {
    int n0 = bx * 32, k0 = by * 32;
    const float* Wp = W + (size_t)bz * K * N;
#pragma unroll
    for (int i = 0; i < 32; i += 8)
        s[ty + i][tx] = Wp[(size_t)(k0 + ty + i) * N + n0 + tx];
    __syncthreads();
#pragma unroll
    for (int i = 0; i < 32; i += 8) {
        int n = n0 + ty + i;
        int k = k0 + tx;
        T[((size_t)bz * N + n) * K + k] = __float2half(s[tx][ty + i]);
    }
}

__global__ void prep_kernel(const float* __restrict__ X,
                            const float* __restrict__ logits,
                            const int*   __restrict__ masks,
                            const float* __restrict__ W1,
                            const float* __restrict__ W2) {
    __shared__ float s[32][33];
    const int blk = blockIdx.x;
    const int tid = threadIdx.x;
    const int tx = tid & 31, ty = tid >> 5;

    if (blk < 4096) {
        // x -> fp16, 4 elems/thread via float4
        size_t i4 = (size_t)blk * 256 + tid;
        float4 v = ((const float4*)X)[i4];
        __half hh[4] = {__float2half(v.x), __float2half(v.y),
                        __float2half(v.z), __float2half(v.w)};
        *(uint2*)(g_x + i4 * 4) = *(uint2*)hh;
    } else if (blk < 12288) {
        int i = blk - 4096;                        // W1: bx<64, by<16, bz<8
        transpose_sec(W1, g_w1t, DM_, FF_, i & 63, (i >> 6) & 15, i >> 10, tx, ty, s);
    } else if (blk < 20480) {
        int i = blk - 12288;                       // W2: bx<16, by<64, bz<8
        transpose_sec(W2, g_w2t, FF_, DM_, i & 15, (i >> 4) & 63, i >> 10, tx, ty, s);
    } else {
        // gates
        int b = tid;
        if (b >= B_) return;
        float p[E_];
        float mx = -1e30f;
#pragma unroll
        for (int i = 0; i < E_; i++) { p[i] = logits[b * E_ + i]; mx = fmaxf(mx, p[i]); }
        float sum = 0.0f;
#pragma unroll
        for (int i = 0; i < E_; i++) { p[i] = expf(p[i] - mx); sum += p[i]; }
        float inv = 1.0f / sum;
#pragma unroll
        for (int i = 0; i < E_; i++) p[i] = (masks[b * E_ + i] == 1) ? p[i] * inv : 0.0f;
        int i1 = 0;
#pragma unroll
        for (int i = 1; i < E_; i++) if (p[i] > p[i1]) i1 = i;
        int i2 = -1;
#pragma unroll
        for (int i = 0; i < E_; i++) {
            if (i == i1) continue;
            if (i2 < 0 || p[i] > p[i2]) i2 = i;
        }
        float denom = p[i1] + p[i2] + 1e-9f;
        g_pair_e[2 * b + 0] = i1;  g_pair_g[2 * b + 0] = p[i1] / denom;
        g_pair_e[2 * b + 1] = i2;  g_pair_g[2 * b + 1] = p[i2] / denom;
    }
}

// ---------------------------------------------------------------------------
// GEMM1 (fp16 1-term, co-resident): gh = fp16( g * gelu(x @ W1[e] + b1[e]) )
// BM=128, BN=128, kc=64; stage = A16+B16 = 32KB; 3 stages (96KB) -> 2 CTAs/SM.
// 256 threads, 8 warps 4x2, warp tile 32x64 (MF=2, NF=8). Grid (16,2,64)=2048.
// ---------------------------------------------------------------------------
#define G1_STAGE  32768u
#define G1_B_O    16384u
#define G1_SMEM   (3 * 32768)

__global__ void __launch_bounds__(256, 2)
gemm1_mma(const float* __restrict__ b1p) {
    extern __shared__ __align__(128) char smem[];
    const int tid = threadIdx.x, lane = tid & 31, wid = tid >> 5;
    const int pair = blockIdx.z;
    const int e = g_pair_e[pair];
    const float g = g_pair_g[pair];
    const int m0 = blockIdx.y * 128, n0 = blockIdx.x * 128;

    const __half* Abase = g_x   + ((size_t)(pair >> 1) * L_ + m0) * DM_;
    const __half* Bbase = g_w1t + ((size_t)e * FF_ + n0) * DM_;

    uint32_t s0 = smem_u32(smem);
    const int wm = (wid >> 1) * 32, wn = (wid & 1) * 64;   // warp tile 32x64

    float acc[2][8][4] = {};
    const int NC = 8;   // 512 / 64

#define G1_LOAD(c, buf) do { int _k = (c) * 64; uint32_t _d = s0 + (buf) * G1_STAGE; \
        load_tile<128, 256>(_d,          Abase + _k, DM_, tid); \
        load_tile<128, 256>(_d + G1_B_O, Bbase + _k, DM_, tid); \
        CP_COMMIT(); } while (0)

    G1_LOAD(0, 0);
    G1_LOAD(1, 1);
    for (int c = 0; c < NC; c++) {
        if (c == NC - 1) asm volatile("cp.async.wait_group 0;" ::: "memory");
        else             asm volatile("cp.async.wait_group 1;" ::: "memory");
        __syncthreads();   // tile c visible; all warps done with buf (c+2)%3 (last read at c-1)
        if (c + 2 < NC) G1_LOAD(c + 2, (uint32_t)((c + 2) % 3));
        uint32_t sb = s0 + (uint32_t)(c % 3) * G1_STAGE;
        compute_single<2, 8>(acc, sb, sb + G1_B_O, wm, wn, lane);
    }
#undef G1_LOAD

    // epilogue: +bias, gelu, *gate, store single fp16
    const float* b1e = b1p + (size_t)e * FF_;
#pragma unroll
    for (int mf = 0; mf < 2; mf++) {
#pragma unroll
        for (int h = 0; h < 2; h++) {
            int r = m0 + wm + mf * 16 + (lane >> 2) + 8 * h;
            __half* rowp = g_gh + ((size_t)pair * L_ + r) * FF_;
#pragma unroll
            for (int nf = 0; nf < 8; nf++) {
                int n = n0 + wn + nf * 8 + (lane & 3) * 2;
                float v0 = acc[mf][nf][2 * h + 0] + __ldg(b1e + n);
                float v1 = acc[mf][nf][2 * h + 1] + __ldg(b1e + n + 1);
                __half hv[2] = {__float2half(gelu_exact(v0) * g),
                                __float2half(gelu_exact(v1) * g)};
                *(uint32_t*)(rowp + n) = *(uint32_t*)hv;
            }
        }
    }
}

// ---------------------------------------------------------------------------
// GEMM2 (R15 measured-best): out[b] = sum_slot gh[b,slot] @ W2[e_slot] + bias
// BM=128, BN=64, kc=64; stage = A16+B8 = 24KB; 3 stages (72KB) -> 2 CTAs/SM.
// 256 threads, 8 warps 4x2, warp tile 32x32. Grid (8,2,32) = 512 CTAs.
// Virtual K = 2 slots * 2048 (64 chunks); 1 sync/iter.
// ---------------------------------------------------------------------------
#define H2_STAGE  24576u
#define H2_B_O    16384u
#define H2_SMEM   (3 * 24576)

__global__ void __launch_bounds__(256, 2)
gemm2_mma(const float* __restrict__ b2p, float* __restrict__ out) {
    extern __shared__ __align__(128) char smem[];
    const int tid = threadIdx.x, lane = tid & 31, wid = tid >> 5;
    const int bb = blockIdx.z;
    const int m0 = blockIdx.y * 128, n0 = blockIdx.x * 64;
    const int e0 = g_pair_e[2 * bb + 0], e1 = g_pair_e[2 * bb + 1];
    const float g0 = g_pair_g[2 * bb + 0], g1 = g_pair_g[2 * bb + 1];

    const __half* Ab[2] = {
        g_gh + ((size_t)(2 * bb + 0) * L_ + m0) * FF_,
        g_gh + ((size_t)(2 * bb + 1) * L_ + m0) * FF_
    };
    const __half* Bb[2] = {
        g_w2t + ((size_t)e0 * DM_ + n0) * FF_,
        g_w2t + ((size_t)e1 * DM_ + n0) * FF_
    };

    uint32_t s0 = smem_u32(smem);
    const int wm = (wid >> 1) * 32, wn = (wid & 1) * 32;   // warp tile 32x32

    float acc[2][4][4] = {};
    const int NC = 64;   // 2 slots * (2048/64)

#define G2_LOAD(c, buf) do { \
        int _sl = (c) >> 5; int _k = ((c) & 31) * 64; uint32_t _d = s0 + (buf) * H2_STAGE; \
        load_tile<128, 256>(_d,          Ab[_sl] + _k, FF_, tid); \
        load_tile<64, 256> (_d + H2_B_O, Bb[_sl] + _k, FF_, tid); \
        CP_COMMIT(); } while (0)

    G2_LOAD(0, 0);
    G2_LOAD(1, 1);
    for (int c = 0; c < NC; c++) {
        if (c == NC - 1) asm volatile("cp.async.wait_group 0;" ::: "memory");
        else             asm volatile("cp.async.wait_group 1;" ::: "memory");
        __syncthreads();
        if (c + 2 < NC) G2_LOAD(c + 2, (uint32_t)((c + 2) % 3));
        uint32_t sb = s0 + (uint32_t)(c % 3) * H2_STAGE;
        compute_single<2, 4>(acc, sb, sb + H2_B_O, wm, wn, lane);
    }
#undef G2_LOAD

    const float* b2e0 = b2p + (size_t)e0 * DM_;
    const float* b2e1 = b2p + (size_t)e1 * DM_;
#pragma unroll
    for (int mf = 0; mf < 2; mf++) {
#pragma unroll
        for (int h = 0; h < 2; h++) {
            int r = m0 + wm + mf * 16 + (lane >> 2) + 8 * h;
            float* op = out + ((size_t)bb * L_ + r) * DM_;
#pragma unroll
            for (int nf = 0; nf < 4; nf++) {
                int n = n0 + wn + nf * 8 + (lane & 3) * 2;
                float2 v;
                v.x = acc[mf][nf][2 * h + 0] + g0 * __ldg(b2e0 + n)     + g1 * __ldg(b2e1 + n);
                v.y = acc[mf][nf][2 * h + 1] + g0 * __ldg(b2e0 + n + 1) + g1 * __ldg(b2e1 + n + 1);
                *(float2*)(op + n) = v;
            }
        }
    }
}

// ---------------------------------------------------------------------------
// launch — kernel launches + idempotent attribute opt-ins (no statics)
// ---------------------------------------------------------------------------
extern "C" void kernel_launch(void* const* d_in, const int* in_sizes, int n_in,
                              void* d_out, int out_size) {
    const float* x      = (const float*)d_in[0];
    const float* logits = (const float*)d_in[1];
    const int*   masks  = (const int*)  d_in[2];
    const float* W1     = (const float*)d_in[3];
    const float* b1     = (const float*)d_in[4];
    const float* W2     = (const float*)d_in[5];
    const float* b2     = (const float*)d_in[6];
    float* out = (float*)d_out;

    cudaFuncSetAttribute(gemm1_mma, cudaFuncAttributeMaxDynamicSharedMemorySize, G1_SMEM);
    cudaFuncSetAttribute(gemm2_mma, cudaFuncAttributeMaxDynamicSharedMemorySize, H2_SMEM);

    prep_kernel<<<20481, 256>>>(x, logits, masks, W1, W2);

    gemm1_mma<<<dim3(FF_ / 128, L_ / 128, NPAIR), 256, G1_SMEM>>>(b1);
    gemm2_mma<<<dim3(DM_ / 64, L_ / 128, B_), 256, H2_SMEM>>>(b2, out);
}